// round 9
// baseline (speedup 1.0000x reference)
#include <cuda_runtime.h>
#include <cuda_bf16.h>
#include <cstdint>

// out[64,11008] = x[64,4096] @ (Wq*scale)^T + bias
// v6: EXACT v3 GEMM (proven 55.8us) with SPLITS 8 -> 16 to cut wave-quantization
//     tail (688 -> 1376 CTAs on 296 resident slots). Nothing else changed.

#define M_DIM 64
#define K_DIM 4096
#define N_DIM 11008

#define SPLITS 16
#define KSR    256          // real k per split
#define BKR    64           // real k per stage
#define NST    (KSR / BKR)  // 4 stages per CTA
#define BKE    128          // effective k per stage (hi/lo)
#define SA     136          // smem row stride in bf16 elems (128 + 8 pad)
#define BN     128          // CTA n-tile
#define THREADS 256

__device__ __align__(16) __nv_bfloat16 g_Axl[M_DIM * 8192];          // 1 MB
__device__ float g_part[SPLITS * M_DIM * N_DIM];                     // 45 MB

__device__ __forceinline__ unsigned pack_bf2(__nv_bfloat16 a, __nv_bfloat16 b) {
    return (unsigned)__bfloat16_as_ushort(a) | ((unsigned)__bfloat16_as_ushort(b) << 16);
}

// ---------------------------------------------------------------------------
// Kernel 1: x[64,4096] f32 -> g_Axl[64,8192] bf16, permuted hi/lo layout.
// Per 16-real-k block j: 32 keff slots; slot(sp,b,qp,e) = sp*16 + b*8 + 2qp + e
//   real k = 16j + 4qp + 2sp + e ; b=0 -> hi(x), b=1 -> lo(x)
// ---------------------------------------------------------------------------
__global__ void convx_kernel(const float* __restrict__ x) {
    int t = blockIdx.x * blockDim.x + threadIdx.x;   // 0..16383
    int m  = t >> 8;          // 0..63
    int st = (t >> 2) & 63;   // 64-real-k super-stage
    int j  = t & 3;           // 16-real-k block

    float fx[16];
    const float4* src = (const float4*)(x + m * K_DIM + st * 64 + j * 16);
    #pragma unroll
    for (int q = 0; q < 4; ++q) ((float4*)fx)[q] = src[q];

    unsigned u[16];
    #pragma unroll
    for (int sp = 0; sp < 2; ++sp) {
        #pragma unroll
        for (int qp = 0; qp < 4; ++qp) {
            int kl = 4 * qp + 2 * sp;
            float a = fx[kl], c = fx[kl + 1];
            __nv_bfloat16 ha = __float2bfloat16_rn(a);
            __nv_bfloat16 hc = __float2bfloat16_rn(c);
            float la = a - __bfloat162float(ha);
            float lc = c - __bfloat162float(hc);
            u[sp * 8 + qp]     = pack_bf2(ha, hc);
            u[sp * 8 + 4 + qp] = pack_bf2(__float2bfloat16_rn(la), __float2bfloat16_rn(lc));
        }
    }
    uint4* dst = (uint4*)(g_Axl + m * 8192 + st * 128 + j * 32);
    #pragma unroll
    for (int q = 0; q < 4; ++q) dst[q] = ((const uint4*)u)[q];
}

// ---------------------------------------------------------------------------
// Kernel 2: split-K GEMM.  CTA: 8 warps, warp = M64 x N16.  grid (86, 16).
// ---------------------------------------------------------------------------
#define MMA16816(d, a0, a1, a2, a3, b)                                          \
    asm volatile(                                                               \
        "mma.sync.aligned.m16n8k16.row.col.f32.bf16.bf16.f32 "                  \
        "{%0,%1,%2,%3}, {%4,%5,%6,%7}, {%8,%9}, {%0,%1,%2,%3};\n"               \
        : "+f"(d[0]), "+f"(d[1]), "+f"(d[2]), "+f"(d[3])                        \
        : "r"(a0), "r"(a1), "r"(a2), "r"(a3), "r"(b), "r"(b))

__device__ __forceinline__ void issue_a(uint32_t adst0, const __nv_bfloat16* agsrc,
                                        int kt, int buf) {
    #pragma unroll
    for (int j = 0; j < 4; ++j) {
        uint32_t d = adst0 + buf * (M_DIM * SA * 2) + j * (16 * SA * 2);
        const void* s = agsrc + kt * BKE + (size_t)j * 16 * 8192;
        asm volatile("cp.async.ca.shared.global [%0], [%1], 16;\n"
                     :: "r"(d), "l"(s));
    }
}

__global__ __launch_bounds__(THREADS, 2)
void qgemm_kernel(const int* __restrict__ wq, float* __restrict__ part) {
    __shared__ __align__(16) __nv_bfloat16 As[2][M_DIM * SA];

    const int tid  = threadIdx.x;
    const int lane = tid & 31;
    const int wid  = tid >> 5;
    const int qp   = lane & 3;
    const int g    = lane >> 2;
    const int bn0   = blockIdx.x * BN;
    const int split = blockIdx.y;

    uint32_t sb;
    { void* p = (void*)As;
      asm("{.reg .u64 t; cvta.to.shared.u64 t, %1; cvt.u32.u64 %0, t;}"
          : "=r"(sb) : "l"(p)); }

    // ---- A cp.async mapping: thread copies 4 x 16B per stage
    const int acol = tid & 15;            // 16B chunk within keff-128 row
    const int arow = tid >> 4;            // base row, +16 per j
    const __nv_bfloat16* agsrc = g_Axl + (size_t)arow * 8192 + split * (KSR * 2) + acol * 8;
    const uint32_t adst0 = sb + (uint32_t)((arow * SA + acol * 8) * 2);

    // ---- B pointers: nfrag f row = bn0 + wid*16 + f*8 + g
    const int* wg0 = wq + (size_t)(bn0 + wid * 16 + g) * K_DIM + split * KSR + 4 * qp;
    const int* wg1 = wg0 + (size_t)8 * K_DIM;

    int4 Bn[2][4];

    // ---- prologue: stage 0
    issue_a(adst0, agsrc, 0, 0);
    asm volatile("cp.async.commit_group;\n");
    #pragma unroll
    for (int j = 0; j < 4; ++j) {
        Bn[0][j] = *(const int4*)(wg0 + 16 * j);
        Bn[1][j] = *(const int4*)(wg1 + 16 * j);
    }

    float acc[4][2][4];
    #pragma unroll
    for (int a = 0; a < 4; ++a)
        #pragma unroll
        for (int b = 0; b < 2; ++b)
            #pragma unroll
            for (int c = 0; c < 4; ++c) acc[a][b][c] = 0.0f;

    const uint32_t aptr = sb + (uint32_t)(((lane & 15) * SA + (lane >> 4) * 8) * 2);

    for (int kt = 0; kt < NST; ++kt) {
        if (kt + 1 < NST) issue_a(adst0, agsrc, kt + 1, (kt + 1) & 1);
        asm volatile("cp.async.commit_group;\n");
        if (kt + 1 < NST) asm volatile("cp.async.wait_group 1;\n");
        else              asm volatile("cp.async.wait_group 0;\n");
        __syncthreads();

        const uint32_t abuf = aptr + (kt & 1) * (M_DIM * SA * 2);
        const int* nw0 = wg0 + (kt + 1) * BKR;
        const int* nw1 = wg1 + (kt + 1) * BKR;
        const bool pf = (kt + 1 < NST);

        #pragma unroll
        for (int s = 0; s < 8; ++s) {
            const int j = s >> 1;
            int v0x, v0y, v1x, v1y;
            if ((s & 1) == 0) { v0x = Bn[0][j].x; v0y = Bn[0][j].y;
                                v1x = Bn[1][j].x; v1y = Bn[1][j].y; }
            else              { v0x = Bn[0][j].z; v0y = Bn[0][j].w;
                                v1x = Bn[1][j].z; v1y = Bn[1][j].w; }
            float f0 = (float)v0x, f1 = (float)v0y;
            float f2 = (float)v1x, f3 = (float)v1y;
            unsigned bb0, bb1;
            asm("cvt.rn.bf16x2.f32 %0, %1, %2;" : "=r"(bb0) : "f"(f1), "f"(f0));
            asm("cvt.rn.bf16x2.f32 %0, %1, %2;" : "=r"(bb1) : "f"(f3), "f"(f2));

            // refill Bn[*][j] for next stage once consumed (odd s)
            if ((s & 1) == 1 && pf) {
                Bn[0][j] = *(const int4*)(nw0 + 16 * j);
                Bn[1][j] = *(const int4*)(nw1 + 16 * j);
            }

            #pragma unroll
            for (int fm = 0; fm < 4; ++fm) {
                unsigned a0, a1, a2, a3;
                asm volatile(
                    "ldmatrix.sync.aligned.m8n8.x4.shared.b16 {%0,%1,%2,%3}, [%4];\n"
                    : "=r"(a0), "=r"(a1), "=r"(a2), "=r"(a3)
                    : "r"(abuf + fm * (16 * SA * 2) + s * 32));
                MMA16816(acc[fm][0], a0, a1, a2, a3, bb0);
                MMA16816(acc[fm][1], a0, a1, a2, a3, bb1);
            }
        }
        __syncthreads();
    }

    // ---- epilogue: partials to scratch
    float* P = part + (size_t)split * (M_DIM * N_DIM);
    #pragma unroll
    for (int fm = 0; fm < 4; ++fm) {
        const int m0 = fm * 16 + g;
        #pragma unroll
        for (int fn = 0; fn < 2; ++fn) {
            const int n = bn0 + wid * 16 + fn * 8 + 2 * qp;
            *(float2*)(P + (size_t)m0 * N_DIM + n) =
                make_float2(acc[fm][fn][0], acc[fm][fn][1]);
            *(float2*)(P + (size_t)(m0 + 8) * N_DIM + n) =
                make_float2(acc[fm][fn][2], acc[fm][fn][3]);
        }
    }
}

// ---------------------------------------------------------------------------
// Kernel 3: out = scale * (sum of partials) + bias     (float4 vectorized)
// ---------------------------------------------------------------------------
__global__ void reduce_kernel(const float* __restrict__ wscale,
                              const float* __restrict__ bias,
                              float* __restrict__ out) {
    const int TOT4 = M_DIM * N_DIM / 4;
    int i = blockIdx.x * blockDim.x + threadIdx.x;
    if (i >= TOT4) return;
    const float4* P = (const float4*)g_part;
    float sx = 0.0f, sy = 0.0f, sz = 0.0f, sw = 0.0f;
    #pragma unroll
    for (int s = 0; s < SPLITS; ++s) {
        float4 v = P[i + (size_t)s * TOT4];
        sx += v.x; sy += v.y; sz += v.z; sw += v.w;
    }
    const float sc = wscale[0];
    int n = (4 * i) % N_DIM;
    float4 bs = *(const float4*)(bias + n);
    ((float4*)out)[i] = make_float4(sc * sx + bs.x, sc * sy + bs.y,
                                    sc * sz + bs.z, sc * sw + bs.w);
}

extern "C" void kernel_launch(void* const* d_in, const int* in_sizes, int n_in,
                              void* d_out, int out_size) {
    const float* x      = (const float*)d_in[0];
    const int*   wq     = (const int*)  d_in[1];
    const float* wscale = (const float*)d_in[2];
    const float* bias   = (const float*)d_in[3];
    float*       out    = (float*)d_out;

    float* part;
    cudaGetSymbolAddress((void**)&part, g_part);

    convx_kernel<<<128, 128>>>(x);
    qgemm_kernel<<<dim3(N_DIM / BN, SPLITS), THREADS>>>(wq, part);
    reduce_kernel<<<(M_DIM * N_DIM / 4 + 255) / 256, 256>>>(wscale, bias, out);
}

// round 11
// speedup vs baseline: 1.0354x; 1.0354x over previous
#include <cuda_runtime.h>
#include <cuda_bf16.h>
#include <cstdint>

// out[64,11008] = x[64,4096] @ (Wq*scale)^T + bias
// v7: v3's proven split-K(8) HMMA GEMM with the x hi/lo conversion FUSED into
//     the GEMM (x is L2-hot: LDG f32 -> split -> STS replaces cp.async of a
//     preconverted tensor). Kills convx kernel + launch gap + g_Axl round-trip;
//     one __syncthreads per stage. MMA loop / B schedule identical to v3.

#define M_DIM 64
#define K_DIM 4096
#define N_DIM 11008

#define SPLITS 8
#define KSR    512          // real k per split
#define BKR    64           // real k per stage
#define NST    (KSR / BKR)  // 8 stages per CTA
#define BKE    128          // effective k per stage (hi/lo)
#define SA     136          // smem row stride in bf16 elems (128 + 8 pad)
#define BN     128          // CTA n-tile
#define THREADS 256

__device__ float g_part[SPLITS * M_DIM * N_DIM];                     // 22.5 MB

__device__ __forceinline__ unsigned pack_bf2(__nv_bfloat16 a, __nv_bfloat16 b) {
    return (unsigned)__bfloat16_as_ushort(a) | ((unsigned)__bfloat16_as_ushort(b) << 16);
}

// ---------------------------------------------------------------------------
// Split-K GEMM with fused x conversion.
// CTA: 8 warps, warp = M64 x N16.  grid (86, 8).
//
// keff layout per 64-real-k stage (128 slots), per 16-real-k block j:
//   slot(j,sp,b,qp,e) = j*32 + sp*16 + b*8 + 2qp + e
//   real k = 16j + 4qp + 2sp + e ;  b=0 -> hi(x), b=1 -> lo(x)
// B fragment for MMA step s (=2j+sp): thread qp needs real k [16j+4qp+2sp,+2)
// duplicated for hi/lo -> one int4 of W covers both sp of block j.
// ---------------------------------------------------------------------------
#define MMA16816(d, a0, a1, a2, a3, b)                                          \
    asm volatile(                                                               \
        "mma.sync.aligned.m16n8k16.row.col.f32.bf16.bf16.f32 "                  \
        "{%0,%1,%2,%3}, {%4,%5,%6,%7}, {%8,%9}, {%0,%1,%2,%3};\n"               \
        : "+f"(d[0]), "+f"(d[1]), "+f"(d[2]), "+f"(d[3])                        \
        : "r"(a0), "r"(a1), "r"(a2), "r"(a3), "r"(b), "r"(b))

__global__ __launch_bounds__(THREADS, 2)
void qgemm_kernel(const float* __restrict__ x,
                  const int*   __restrict__ wq,
                  float*       __restrict__ part) {
    __shared__ __align__(16) __nv_bfloat16 As[2][M_DIM * SA];

    const int tid  = threadIdx.x;
    const int lane = tid & 31;
    const int wid  = tid >> 5;
    const int qp   = lane & 3;
    const int g    = lane >> 2;
    const int bn0   = blockIdx.x * BN;
    const int split = blockIdx.y;

    // ---- conversion mapping: thread = (row r, 16-k block j)
    const int crow = tid >> 2;            // 0..63
    const int cj   = tid & 3;             // 0..3
    const float* xg = x + (size_t)crow * K_DIM + split * KSR + cj * 16;
    __nv_bfloat16* cdst0 = &As[0][crow * SA + cj * 32];
    __nv_bfloat16* cdst1 = &As[1][crow * SA + cj * 32];

    // ---- B pointers: nfrag f row = bn0 + wid*16 + f*8 + g
    const int* wg0 = wq + (size_t)(bn0 + wid * 16 + g) * K_DIM + split * KSR + 4 * qp;
    const int* wg1 = wg0 + (size_t)8 * K_DIM;

    float xr[16];
    int4  Bn[2][4];

    // ---- prologue: x regs + B regs for stage 0
    #pragma unroll
    for (int q = 0; q < 4; ++q)
        ((float4*)xr)[q] = *(const float4*)(xg + q * 4);
    #pragma unroll
    for (int j = 0; j < 4; ++j) {
        Bn[0][j] = *(const int4*)(wg0 + 16 * j);
        Bn[1][j] = *(const int4*)(wg1 + 16 * j);
    }

    float acc[4][2][4];
    #pragma unroll
    for (int a = 0; a < 4; ++a)
        #pragma unroll
        for (int b = 0; b < 2; ++b)
            #pragma unroll
            for (int c = 0; c < 4; ++c) acc[a][b][c] = 0.0f;

    uint32_t sb;
    { void* p = (void*)As;
      asm("{.reg .u64 t; cvta.to.shared.u64 t, %1; cvt.u32.u64 %0, t;}"
          : "=r"(sb) : "l"(p)); }
    const uint32_t aptr = sb + (uint32_t)(((lane & 15) * SA + (lane >> 4) * 8) * 2);

    for (int kt = 0; kt < NST; ++kt) {
        // ---- convert prefetched x regs -> smem buf kt&1 (hi/lo split)
        {
            unsigned u[16];
            #pragma unroll
            for (int sp = 0; sp < 2; ++sp) {
                #pragma unroll
                for (int q = 0; q < 4; ++q) {
                    int kl = 4 * q + 2 * sp;
                    float a = xr[kl], c = xr[kl + 1];
                    __nv_bfloat16 ha = __float2bfloat16_rn(a);
                    __nv_bfloat16 hc = __float2bfloat16_rn(c);
                    float la = a - __bfloat162float(ha);
                    float lc = c - __bfloat162float(hc);
                    u[sp * 8 + q]     = pack_bf2(ha, hc);
                    u[sp * 8 + 4 + q] = pack_bf2(__float2bfloat16_rn(la),
                                                 __float2bfloat16_rn(lc));
                }
            }
            uint4* dst = (uint4*)((kt & 1) ? cdst1 : cdst0);
            #pragma unroll
            for (int q = 0; q < 4; ++q) dst[q] = ((const uint4*)u)[q];
        }
        __syncthreads();   // buf(kt&1) ready; also fences kt-2's readers (dbl buf)

        // ---- prefetch next stage's x into regs (overlaps MMA loop)
        if (kt + 1 < NST) {
            const float* xn = xg + (kt + 1) * BKR;
            #pragma unroll
            for (int q = 0; q < 4; ++q)
                ((float4*)xr)[q] = *(const float4*)(xn + q * 4);
        }

        const uint32_t abuf = aptr + (kt & 1) * (M_DIM * SA * 2);
        const int* nw0 = wg0 + (kt + 1) * BKR;
        const int* nw1 = wg1 + (kt + 1) * BKR;
        const bool pf = (kt + 1 < NST);

        #pragma unroll
        for (int s = 0; s < 8; ++s) {
            const int j = s >> 1;
            int v0x, v0y, v1x, v1y;
            if ((s & 1) == 0) { v0x = Bn[0][j].x; v0y = Bn[0][j].y;
                                v1x = Bn[1][j].x; v1y = Bn[1][j].y; }
            else              { v0x = Bn[0][j].z; v0y = Bn[0][j].w;
                                v1x = Bn[1][j].z; v1y = Bn[1][j].w; }
            float f0 = (float)v0x, f1 = (float)v0y;
            float f2 = (float)v1x, f3 = (float)v1y;
            unsigned bb0, bb1;
            asm("cvt.rn.bf16x2.f32 %0, %1, %2;" : "=r"(bb0) : "f"(f1), "f"(f0));
            asm("cvt.rn.bf16x2.f32 %0, %1, %2;" : "=r"(bb1) : "f"(f3), "f"(f2));

            // refill Bn[*][j] for next stage once consumed (odd s)
            if ((s & 1) == 1 && pf) {
                Bn[0][j] = *(const int4*)(nw0 + 16 * j);
                Bn[1][j] = *(const int4*)(nw1 + 16 * j);
            }

            #pragma unroll
            for (int fm = 0; fm < 4; ++fm) {
                unsigned a0, a1, a2, a3;
                asm volatile(
                    "ldmatrix.sync.aligned.m8n8.x4.shared.b16 {%0,%1,%2,%3}, [%4];\n"
                    : "=r"(a0), "=r"(a1), "=r"(a2), "=r"(a3)
                    : "r"(abuf + fm * (16 * SA * 2) + s * 32));
                MMA16816(acc[fm][0], a0, a1, a2, a3, bb0);
                MMA16816(acc[fm][1], a0, a1, a2, a3, bb1);
            }
        }
        // no trailing sync: next stage writes the OTHER buffer; the barrier at
        // stage kt+1 orders this stage's reads before stage kt+2's overwrites.
    }

    // ---- epilogue: partials to scratch
    float* P = part + (size_t)split * (M_DIM * N_DIM);
    #pragma unroll
    for (int fm = 0; fm < 4; ++fm) {
        const int m0 = fm * 16 + g;
        #pragma unroll
        for (int fn = 0; fn < 2; ++fn) {
            const int n = bn0 + wid * 16 + fn * 8 + 2 * qp;
            *(float2*)(P + (size_t)m0 * N_DIM + n) =
                make_float2(acc[fm][fn][0], acc[fm][fn][1]);
            *(float2*)(P + (size_t)(m0 + 8) * N_DIM + n) =
                make_float2(acc[fm][fn][2], acc[fm][fn][3]);
        }
    }
}

// ---------------------------------------------------------------------------
// Reduce: out = scale * (sum of partials) + bias     (float4 vectorized)
// ---------------------------------------------------------------------------
__global__ void reduce_kernel(const float* __restrict__ wscale,
                              const float* __restrict__ bias,
                              float* __restrict__ out) {
    const int TOT4 = M_DIM * N_DIM / 4;
    int i = blockIdx.x * blockDim.x + threadIdx.x;
    if (i >= TOT4) return;
    const float4* P = (const float4*)g_part;
    float sx = 0.0f, sy = 0.0f, sz = 0.0f, sw = 0.0f;
    #pragma unroll
    for (int s = 0; s < SPLITS; ++s) {
        float4 v = P[i + (size_t)s * TOT4];
        sx += v.x; sy += v.y; sz += v.z; sw += v.w;
    }
    const float sc = wscale[0];
    int n = (4 * i) % N_DIM;
    float4 bs = *(const float4*)(bias + n);
    ((float4*)out)[i] = make_float4(sc * sx + bs.x, sc * sy + bs.y,
                                    sc * sz + bs.z, sc * sw + bs.w);
}

extern "C" void kernel_launch(void* const* d_in, const int* in_sizes, int n_in,
                              void* d_out, int out_size) {
    const float* x      = (const float*)d_in[0];
    const int*   wq     = (const int*)  d_in[1];
    const float* wscale = (const float*)d_in[2];
    const float* bias   = (const float*)d_in[3];
    float*       out    = (float*)d_out;

    float* part;
    cudaGetSymbolAddress((void**)&part, g_part);

    qgemm_kernel<<<dim3(N_DIM / BN, SPLITS), THREADS>>>(x, wq, part);
    reduce_kernel<<<(M_DIM * N_DIM / 4 + 255) / 256, 256>>>(wscale, bias, out);
}

// round 12
// speedup vs baseline: 1.1704x; 1.1303x over previous
#include <cuda_runtime.h>
#include <cuda_bf16.h>
#include <cstdint>

// out[64,11008] = x[64,4096] @ (Wq*scale)^T + bias
// v8: v3 core (proven 55.8us) + (1) convx 65536 threads, (2) A triple-buffer
//     with single __syncthreads/stage, (3) reduce 2x float4/thread.

#define M_DIM 64
#define K_DIM 4096
#define N_DIM 11008

#define SPLITS 8
#define KSR    512          // real k per split
#define BKR    64           // real k per stage
#define NST    (KSR / BKR)  // 8 stages per CTA
#define BKE    128          // effective k per stage (hi/lo)
#define SA     136          // smem row stride in bf16 elems (128 + 8 pad)
#define NBUF   3
#define ABUF_B (M_DIM * SA * 2)
#define BN     128          // CTA n-tile
#define THREADS 256

__device__ __align__(16) __nv_bfloat16 g_Axl[M_DIM * 8192];          // 1 MB
__device__ float g_part[SPLITS * M_DIM * N_DIM];                     // 22.5 MB

__device__ __forceinline__ unsigned pack_bf2(__nv_bfloat16 a, __nv_bfloat16 b) {
    return (unsigned)__bfloat16_as_ushort(a) | ((unsigned)__bfloat16_as_ushort(b) << 16);
}

// ---------------------------------------------------------------------------
// Kernel 1: x[64,4096] f32 -> g_Axl[64,8192] bf16, permuted hi/lo layout.
// Per 16-real-k block j (32 keff slots): slot(sp,b,q,e) = sp*16 + b*8 + 2q + e
//   real k = 16j + 4q + 2sp + e ; b=0 -> hi(x), b=1 -> lo(x)
// Thread = (m, j, q): one float4 (k = 16j+4q..+3, i.e. sp,e in {0,1}),
// writes 4 uints at block offsets {0,8,16,24} + 2q.  65536 thr, coalesced.
// ---------------------------------------------------------------------------
__global__ void convx_kernel(const float* __restrict__ x) {
    int t = blockIdx.x * blockDim.x + threadIdx.x;   // 0..65535
    int m   = t >> 10;         // 0..63
    int idx = t & 1023;
    int j   = idx >> 2;        // 16-k block 0..255
    int q   = idx & 3;         // qp

    float4 f = *(const float4*)(x + m * K_DIM + j * 16 + q * 4);
    // kl = 4q + 2sp + e: f.x=(sp0,e0) f.y=(sp0,e1) f.z=(sp1,e0) f.w=(sp1,e1)
    __nv_bfloat16 hx = __float2bfloat16_rn(f.x);
    __nv_bfloat16 hy = __float2bfloat16_rn(f.y);
    __nv_bfloat16 hz = __float2bfloat16_rn(f.z);
    __nv_bfloat16 hw = __float2bfloat16_rn(f.w);
    __nv_bfloat16 lx = __float2bfloat16_rn(f.x - __bfloat162float(hx));
    __nv_bfloat16 ly = __float2bfloat16_rn(f.y - __bfloat162float(hy));
    __nv_bfloat16 lz = __float2bfloat16_rn(f.z - __bfloat162float(hz));
    __nv_bfloat16 lw = __float2bfloat16_rn(f.w - __bfloat162float(hw));

    unsigned* base = (unsigned*)(g_Axl + m * 8192 + j * 32 + 2 * q);
    base[0]  = pack_bf2(hx, hy);   // sp0 hi  (slot 2q)
    base[4]  = pack_bf2(lx, ly);   // sp0 lo  (slot 8+2q)
    base[8]  = pack_bf2(hz, hw);   // sp1 hi  (slot 16+2q)
    base[12] = pack_bf2(lz, lw);   // sp1 lo  (slot 24+2q)
}

// ---------------------------------------------------------------------------
// Kernel 2: split-K GEMM.  CTA: 8 warps, warp = M64 x N16.  grid (86, 8).
// A: cp.async triple-buffer, ONE __syncthreads per stage.
// ---------------------------------------------------------------------------
#define MMA16816(d, a0, a1, a2, a3, b)                                          \
    asm volatile(                                                               \
        "mma.sync.aligned.m16n8k16.row.col.f32.bf16.bf16.f32 "                  \
        "{%0,%1,%2,%3}, {%4,%5,%6,%7}, {%8,%9}, {%0,%1,%2,%3};\n"               \
        : "+f"(d[0]), "+f"(d[1]), "+f"(d[2]), "+f"(d[3])                        \
        : "r"(a0), "r"(a1), "r"(a2), "r"(a3), "r"(b), "r"(b))

__device__ __forceinline__ void issue_a(uint32_t adst0, const __nv_bfloat16* agsrc,
                                        int kt, int buf) {
    #pragma unroll
    for (int j = 0; j < 4; ++j) {
        uint32_t d = adst0 + buf * ABUF_B + j * (16 * SA * 2);
        const void* s = agsrc + kt * BKE + (size_t)j * 16 * 8192;
        asm volatile("cp.async.ca.shared.global [%0], [%1], 16;\n"
                     :: "r"(d), "l"(s));
    }
}

__global__ __launch_bounds__(THREADS, 2)
void qgemm_kernel(const int* __restrict__ wq, float* __restrict__ part) {
    __shared__ __align__(16) __nv_bfloat16 As[NBUF][M_DIM * SA];

    const int tid  = threadIdx.x;
    const int lane = tid & 31;
    const int wid  = tid >> 5;
    const int qp   = lane & 3;
    const int g    = lane >> 2;
    const int bn0   = blockIdx.x * BN;
    const int split = blockIdx.y;

    uint32_t sb;
    { void* p = (void*)As;
      asm("{.reg .u64 t; cvta.to.shared.u64 t, %1; cvt.u32.u64 %0, t;}"
          : "=r"(sb) : "l"(p)); }

    // ---- A cp.async mapping: thread copies 4 x 16B per stage
    const int acol = tid & 15;            // 16B chunk within keff-128 row
    const int arow = tid >> 4;            // base row, +16 per j
    const __nv_bfloat16* agsrc = g_Axl + (size_t)arow * 8192 + split * (KSR * 2) + acol * 8;
    const uint32_t adst0 = sb + (uint32_t)((arow * SA + acol * 8) * 2);

    // ---- B pointers: nfrag f row = bn0 + wid*16 + f*8 + g
    const int* wg0 = wq + (size_t)(bn0 + wid * 16 + g) * K_DIM + split * KSR + 4 * qp;
    const int* wg1 = wg0 + (size_t)8 * K_DIM;

    int4 Bn[2][4];

    // ---- prologue: A stages 0,1 in flight; B stage 0 in regs
    issue_a(adst0, agsrc, 0, 0);
    asm volatile("cp.async.commit_group;\n");
    issue_a(adst0, agsrc, 1, 1);
    asm volatile("cp.async.commit_group;\n");
    #pragma unroll
    for (int j = 0; j < 4; ++j) {
        Bn[0][j] = *(const int4*)(wg0 + 16 * j);
        Bn[1][j] = *(const int4*)(wg1 + 16 * j);
    }

    float acc[4][2][4];
    #pragma unroll
    for (int a = 0; a < 4; ++a)
        #pragma unroll
        for (int b = 0; b < 2; ++b)
            #pragma unroll
            for (int c = 0; c < 4; ++c) acc[a][b][c] = 0.0f;

    const uint32_t aptr = sb + (uint32_t)(((lane & 15) * SA + (lane >> 4) * 8) * 2);

    int buf_r = 0;          // buffer holding stage kt
    int buf_w = 2;          // buffer stage kt+2 will be written to

    for (int kt = 0; kt < NST; ++kt) {
        // stage kt complete when <=1 group pending (kt+1 may still fly)
        asm volatile("cp.async.wait_group 1;\n");
        __syncthreads();    // all threads done with stage kt-1's buffer (==buf_w)

        if (kt + 2 < NST) issue_a(adst0, agsrc, kt + 2, buf_w);
        asm volatile("cp.async.commit_group;\n");   // one group per iter (may be empty)

        const uint32_t abuf = aptr + buf_r * ABUF_B;
        const int* nw0 = wg0 + (kt + 1) * BKR;
        const int* nw1 = wg1 + (kt + 1) * BKR;
        const bool pf = (kt + 1 < NST);

        #pragma unroll
        for (int s = 0; s < 8; ++s) {
            const int j = s >> 1;
            int v0x, v0y, v1x, v1y;
            if ((s & 1) == 0) { v0x = Bn[0][j].x; v0y = Bn[0][j].y;
                                v1x = Bn[1][j].x; v1y = Bn[1][j].y; }
            else              { v0x = Bn[0][j].z; v0y = Bn[0][j].w;
                                v1x = Bn[1][j].z; v1y = Bn[1][j].w; }
            float f0 = (float)v0x, f1 = (float)v0y;
            float f2 = (float)v1x, f3 = (float)v1y;
            unsigned bb0, bb1;
            asm("cvt.rn.bf16x2.f32 %0, %1, %2;" : "=r"(bb0) : "f"(f1), "f"(f0));
            asm("cvt.rn.bf16x2.f32 %0, %1, %2;" : "=r"(bb1) : "f"(f3), "f"(f2));

            // refill Bn[*][j] for next stage once consumed (odd s)
            if ((s & 1) == 1 && pf) {
                Bn[0][j] = *(const int4*)(nw0 + 16 * j);
                Bn[1][j] = *(const int4*)(nw1 + 16 * j);
            }

            #pragma unroll
            for (int fm = 0; fm < 4; ++fm) {
                unsigned a0, a1, a2, a3;
                asm volatile(
                    "ldmatrix.sync.aligned.m8n8.x4.shared.b16 {%0,%1,%2,%3}, [%4];\n"
                    : "=r"(a0), "=r"(a1), "=r"(a2), "=r"(a3)
                    : "r"(abuf + fm * (16 * SA * 2) + s * 32));
                MMA16816(acc[fm][0], a0, a1, a2, a3, bb0);
                MMA16816(acc[fm][1], a0, a1, a2, a3, bb1);
            }
        }
        // rotate buffers (no trailing sync: next top-of-stage sync protects buf_w)
        buf_r = (buf_r == 2) ? 0 : buf_r + 1;
        buf_w = (buf_w == 2) ? 0 : buf_w + 1;
    }

    // ---- epilogue: partials to scratch
    float* P = part + (size_t)split * (M_DIM * N_DIM);
    #pragma unroll
    for (int fm = 0; fm < 4; ++fm) {
        const int m0 = fm * 16 + g;
        #pragma unroll
        for (int fn = 0; fn < 2; ++fn) {
            const int n = bn0 + wid * 16 + fn * 8 + 2 * qp;
            *(float2*)(P + (size_t)m0 * N_DIM + n) =
                make_float2(acc[fm][fn][0], acc[fm][fn][1]);
            *(float2*)(P + (size_t)(m0 + 8) * N_DIM + n) =
                make_float2(acc[fm][fn][2], acc[fm][fn][3]);
        }
    }
}

// ---------------------------------------------------------------------------
// Kernel 3: out = scale * (sum of partials) + bias.  2 float4 per thread,
// all 16 loads batched for ILP.
// ---------------------------------------------------------------------------
__global__ void reduce_kernel(const float* __restrict__ wscale,
                              const float* __restrict__ bias,
                              float* __restrict__ out) {
    const int TOT4 = M_DIM * N_DIM / 4;          // 176128
    int i0 = (blockIdx.x * blockDim.x + threadIdx.x) * 2;
    if (i0 >= TOT4) return;
    const float4* P = (const float4*)g_part;

    float4 v[SPLITS][2];
    #pragma unroll
    for (int s = 0; s < SPLITS; ++s) {
        v[s][0] = P[i0     + (size_t)s * TOT4];
        v[s][1] = P[i0 + 1 + (size_t)s * TOT4];
    }
    const float sc = wscale[0];
    #pragma unroll
    for (int u = 0; u < 2; ++u) {
        float sx = 0.0f, sy = 0.0f, sz = 0.0f, sw = 0.0f;
        #pragma unroll
        for (int s = 0; s < SPLITS; ++s) {
            sx += v[s][u].x; sy += v[s][u].y; sz += v[s][u].z; sw += v[s][u].w;
        }
        int n = (4 * (i0 + u)) % N_DIM;
        float4 bs = *(const float4*)(bias + n);
        ((float4*)out)[i0 + u] = make_float4(sc * sx + bs.x, sc * sy + bs.y,
                                             sc * sz + bs.z, sc * sw + bs.w);
    }
}

extern "C" void kernel_launch(void* const* d_in, const int* in_sizes, int n_in,
                              void* d_out, int out_size) {
    const float* x      = (const float*)d_in[0];
    const int*   wq     = (const int*)  d_in[1];
    const float* wscale = (const float*)d_in[2];
    const float* bias   = (const float*)d_in[3];
    float*       out    = (float*)d_out;

    float* part;
    cudaGetSymbolAddress((void**)&part, g_part);

    convx_kernel<<<512, 128>>>(x);
    qgemm_kernel<<<dim3(N_DIM / BN, SPLITS), THREADS>>>(wq, part);
    reduce_kernel<<<(M_DIM * N_DIM / 8 + 255) / 256, 256>>>(wscale, bias, out);
}

// round 13
// speedup vs baseline: 1.2599x; 1.0765x over previous
#include <cuda_runtime.h>
#include <cuda_bf16.h>
#include <cstdint>

// out[64,11008] = x[64,4096] @ (Wq*scale)^T + bias
// v9: v3's EXACT GEMM loop (proven 55.8us) with the split-K reduction deleted:
//     prep kernel writes bias into out AND converts x (merged); GEMM epilogue
//     atomicAdds scale*acc into out (L2-resident, 8-way). 2 launches, no
//     partials scratch round-trip.

#define M_DIM 64
#define K_DIM 4096
#define N_DIM 11008

#define SPLITS 8
#define KSR    512          // real k per split
#define BKR    64           // real k per stage
#define NST    (KSR / BKR)  // 8 stages per CTA
#define BKE    128          // effective k per stage (hi/lo)
#define SA     136          // smem row stride in bf16 elems (128 + 8 pad)
#define BN     128          // CTA n-tile
#define THREADS 256

__device__ __align__(16) __nv_bfloat16 g_Axl[M_DIM * 8192];          // 1 MB

__device__ __forceinline__ unsigned pack_bf2(__nv_bfloat16 a, __nv_bfloat16 b) {
    return (unsigned)__bfloat16_as_ushort(a) | ((unsigned)__bfloat16_as_ushort(b) << 16);
}

// ---------------------------------------------------------------------------
// Kernel 1 (prep): every thread writes one float4 of out = bias; the first
// 65536 threads also convert one float4 of x into the permuted hi/lo layout.
// Layout per 16-real-k block j (32 keff slots): slot(sp,b,q,e)=sp*16+b*8+2q+e
//   real k = 16j + 4q + 2sp + e ; b=0 -> hi(x), b=1 -> lo(x)
// ---------------------------------------------------------------------------
__global__ void prep_kernel(const float* __restrict__ x,
                            const float* __restrict__ bias,
                            float* __restrict__ out) {
    int t = blockIdx.x * blockDim.x + threadIdx.x;   // 0..176127

    // ---- out init with bias (float4; N_DIM % 4 == 0)
    {
        int n4 = (4 * t) % N_DIM;
        float4 bs = *(const float4*)(bias + n4);
        ((float4*)out)[t] = bs;
    }

    // ---- x conversion (first 65536 threads)
    if (t < 65536) {
        int m   = t >> 10;         // 0..63
        int idx = t & 1023;
        int j   = idx >> 2;        // 16-k block 0..255
        int q   = idx & 3;         // qp

        float4 f = *(const float4*)(x + m * K_DIM + j * 16 + q * 4);
        __nv_bfloat16 hx = __float2bfloat16_rn(f.x);
        __nv_bfloat16 hy = __float2bfloat16_rn(f.y);
        __nv_bfloat16 hz = __float2bfloat16_rn(f.z);
        __nv_bfloat16 hw = __float2bfloat16_rn(f.w);
        __nv_bfloat16 lx = __float2bfloat16_rn(f.x - __bfloat162float(hx));
        __nv_bfloat16 ly = __float2bfloat16_rn(f.y - __bfloat162float(hy));
        __nv_bfloat16 lz = __float2bfloat16_rn(f.z - __bfloat162float(hz));
        __nv_bfloat16 lw = __float2bfloat16_rn(f.w - __bfloat162float(hw));

        unsigned* base = (unsigned*)(g_Axl + m * 8192 + j * 32 + 2 * q);
        base[0]  = pack_bf2(hx, hy);   // sp0 hi
        base[4]  = pack_bf2(lx, ly);   // sp0 lo
        base[8]  = pack_bf2(hz, hw);   // sp1 hi
        base[12] = pack_bf2(lz, lw);   // sp1 lo
    }
}

// ---------------------------------------------------------------------------
// Kernel 2: split-K GEMM, v3 loop verbatim.  CTA: 8 warps, warp = M64 x N16.
// grid (86, 8).  Epilogue: atomicAdd(scale*acc) into out.
// ---------------------------------------------------------------------------
#define MMA16816(d, a0, a1, a2, a3, b)                                          \
    asm volatile(                                                               \
        "mma.sync.aligned.m16n8k16.row.col.f32.bf16.bf16.f32 "                  \
        "{%0,%1,%2,%3}, {%4,%5,%6,%7}, {%8,%9}, {%0,%1,%2,%3};\n"               \
        : "+f"(d[0]), "+f"(d[1]), "+f"(d[2]), "+f"(d[3])                        \
        : "r"(a0), "r"(a1), "r"(a2), "r"(a3), "r"(b), "r"(b))

__device__ __forceinline__ void issue_a(uint32_t adst0, const __nv_bfloat16* agsrc,
                                        int kt, int buf) {
    #pragma unroll
    for (int j = 0; j < 4; ++j) {
        uint32_t d = adst0 + buf * (M_DIM * SA * 2) + j * (16 * SA * 2);
        const void* s = agsrc + kt * BKE + (size_t)j * 16 * 8192;
        asm volatile("cp.async.ca.shared.global [%0], [%1], 16;\n"
                     :: "r"(d), "l"(s));
    }
}

__global__ __launch_bounds__(THREADS, 2)
void qgemm_kernel(const int* __restrict__ wq,
                  const float* __restrict__ wscale,
                  float* __restrict__ out) {
    __shared__ __align__(16) __nv_bfloat16 As[2][M_DIM * SA];

    const int tid  = threadIdx.x;
    const int lane = tid & 31;
    const int wid  = tid >> 5;
    const int qp   = lane & 3;
    const int g    = lane >> 2;
    const int bn0   = blockIdx.x * BN;
    const int split = blockIdx.y;

    uint32_t sb;
    { void* p = (void*)As;
      asm("{.reg .u64 t; cvta.to.shared.u64 t, %1; cvt.u32.u64 %0, t;}"
          : "=r"(sb) : "l"(p)); }

    // ---- A cp.async mapping: thread copies 4 x 16B per stage
    const int acol = tid & 15;            // 16B chunk within keff-128 row
    const int arow = tid >> 4;            // base row, +16 per j
    const __nv_bfloat16* agsrc = g_Axl + (size_t)arow * 8192 + split * (KSR * 2) + acol * 8;
    const uint32_t adst0 = sb + (uint32_t)((arow * SA + acol * 8) * 2);

    // ---- B pointers: nfrag f row = bn0 + wid*16 + f*8 + g
    const int* wg0 = wq + (size_t)(bn0 + wid * 16 + g) * K_DIM + split * KSR + 4 * qp;
    const int* wg1 = wg0 + (size_t)8 * K_DIM;

    int4 Bn[2][4];

    // ---- prologue: stage 0
    issue_a(adst0, agsrc, 0, 0);
    asm volatile("cp.async.commit_group;\n");
    #pragma unroll
    for (int j = 0; j < 4; ++j) {
        Bn[0][j] = *(const int4*)(wg0 + 16 * j);
        Bn[1][j] = *(const int4*)(wg1 + 16 * j);
    }

    float acc[4][2][4];
    #pragma unroll
    for (int a = 0; a < 4; ++a)
        #pragma unroll
        for (int b = 0; b < 2; ++b)
            #pragma unroll
            for (int c = 0; c < 4; ++c) acc[a][b][c] = 0.0f;

    const uint32_t aptr = sb + (uint32_t)(((lane & 15) * SA + (lane >> 4) * 8) * 2);

    for (int kt = 0; kt < NST; ++kt) {
        if (kt + 1 < NST) issue_a(adst0, agsrc, kt + 1, (kt + 1) & 1);
        asm volatile("cp.async.commit_group;\n");
        if (kt + 1 < NST) asm volatile("cp.async.wait_group 1;\n");
        else              asm volatile("cp.async.wait_group 0;\n");
        __syncthreads();

        const uint32_t abuf = aptr + (kt & 1) * (M_DIM * SA * 2);
        const int* nw0 = wg0 + (kt + 1) * BKR;
        const int* nw1 = wg1 + (kt + 1) * BKR;
        const bool pf = (kt + 1 < NST);

        #pragma unroll
        for (int s = 0; s < 8; ++s) {
            const int j = s >> 1;
            int v0x, v0y, v1x, v1y;
            if ((s & 1) == 0) { v0x = Bn[0][j].x; v0y = Bn[0][j].y;
                                v1x = Bn[1][j].x; v1y = Bn[1][j].y; }
            else              { v0x = Bn[0][j].z; v0y = Bn[0][j].w;
                                v1x = Bn[1][j].z; v1y = Bn[1][j].w; }
            float f0 = (float)v0x, f1 = (float)v0y;
            float f2 = (float)v1x, f3 = (float)v1y;
            unsigned bb0, bb1;
            asm("cvt.rn.bf16x2.f32 %0, %1, %2;" : "=r"(bb0) : "f"(f1), "f"(f0));
            asm("cvt.rn.bf16x2.f32 %0, %1, %2;" : "=r"(bb1) : "f"(f3), "f"(f2));

            // refill Bn[*][j] for next stage once consumed (odd s)
            if ((s & 1) == 1 && pf) {
                Bn[0][j] = *(const int4*)(nw0 + 16 * j);
                Bn[1][j] = *(const int4*)(nw1 + 16 * j);
            }

            #pragma unroll
            for (int fm = 0; fm < 4; ++fm) {
                unsigned a0, a1, a2, a3;
                asm volatile(
                    "ldmatrix.sync.aligned.m8n8.x4.shared.b16 {%0,%1,%2,%3}, [%4];\n"
                    : "=r"(a0), "=r"(a1), "=r"(a2), "=r"(a3)
                    : "r"(abuf + fm * (16 * SA * 2) + s * 32));
                MMA16816(acc[fm][0], a0, a1, a2, a3, bb0);
                MMA16816(acc[fm][1], a0, a1, a2, a3, bb1);
            }
        }
        __syncthreads();
    }

    // ---- epilogue: atomicAdd scale*acc into bias-initialized out
    const float sc = wscale[0];
    #pragma unroll
    for (int fm = 0; fm < 4; ++fm) {
        const int m0 = fm * 16 + g;
        #pragma unroll
        for (int fn = 0; fn < 2; ++fn) {
            const int n = bn0 + wid * 16 + fn * 8 + 2 * qp;
            atomicAdd(out + (size_t)m0 * N_DIM + n,           sc * acc[fm][fn][0]);
            atomicAdd(out + (size_t)m0 * N_DIM + n + 1,       sc * acc[fm][fn][1]);
            atomicAdd(out + (size_t)(m0 + 8) * N_DIM + n,     sc * acc[fm][fn][2]);
            atomicAdd(out + (size_t)(m0 + 8) * N_DIM + n + 1, sc * acc[fm][fn][3]);
        }
    }
}

extern "C" void kernel_launch(void* const* d_in, const int* in_sizes, int n_in,
                              void* d_out, int out_size) {
    const float* x      = (const float*)d_in[0];
    const int*   wq     = (const int*)  d_in[1];
    const float* wscale = (const float*)d_in[2];
    const float* bias   = (const float*)d_in[3];
    float*       out    = (float*)d_out;

    // 176128 threads = one float4 of out each; first 65536 also convert x.
    prep_kernel<<<688, 256>>>(x, bias, out);
    qgemm_kernel<<<dim3(N_DIM / BN, SPLITS), THREADS>>>(wq, wscale, out);
}

// round 16
// speedup vs baseline: 1.3120x; 1.0413x over previous
#include <cuda_runtime.h>
#include <cuda_bf16.h>
#include <cstdint>

// out[64,11008] = x[64,4096] @ (Wq*scale)^T + bias
// v10: v9 (atomic split-K epilogue, merged prep) with the GEMM CTA reshaped to
//      4 warps x (M64 x N32): halves A-side ldmatrix L1 wavefronts (the 73.7%
//      pipe), B still read exactly once, no spills ((128,3): cap 170 regs),
//      occ 3 CTAs/SM, waves 2.32 -> 1.55. Pipeline structure = v3 verbatim.

#define M_DIM 64
#define K_DIM 4096
#define N_DIM 11008

#define SPLITS 8
#define KSR    512          // real k per split
#define BKR    64           // real k per stage
#define NST    (KSR / BKR)  // 8 stages per CTA
#define BKE    128          // effective k per stage (hi/lo)
#define SA     136          // smem row stride in bf16 elems (128 + 8 pad)
#define BN     128          // CTA n-tile
#define THREADS 128

__device__ __align__(16) __nv_bfloat16 g_Axl[M_DIM * 8192];          // 1 MB

__device__ __forceinline__ unsigned pack_bf2(__nv_bfloat16 a, __nv_bfloat16 b) {
    return (unsigned)__bfloat16_as_ushort(a) | ((unsigned)__bfloat16_as_ushort(b) << 16);
}

// ---------------------------------------------------------------------------
// Kernel 1 (prep): every thread writes one float4 of out = bias; the first
// 65536 threads also convert one float4 of x into the permuted hi/lo layout.
// Layout per 16-real-k block j (32 keff slots): slot(sp,b,q,e)=sp*16+b*8+2q+e
//   real k = 16j + 4q + 2sp + e ; b=0 -> hi(x), b=1 -> lo(x)
// ---------------------------------------------------------------------------
__global__ void prep_kernel(const float* __restrict__ x,
                            const float* __restrict__ bias,
                            float* __restrict__ out) {
    int t = blockIdx.x * blockDim.x + threadIdx.x;   // 0..176127

    {
        int n4 = (4 * t) % N_DIM;
        float4 bs = *(const float4*)(bias + n4);
        ((float4*)out)[t] = bs;
    }

    if (t < 65536) {
        int m   = t >> 10;         // 0..63
        int idx = t & 1023;
        int j   = idx >> 2;        // 16-k block 0..255
        int q   = idx & 3;         // qp

        float4 f = *(const float4*)(x + m * K_DIM + j * 16 + q * 4);
        __nv_bfloat16 hx = __float2bfloat16_rn(f.x);
        __nv_bfloat16 hy = __float2bfloat16_rn(f.y);
        __nv_bfloat16 hz = __float2bfloat16_rn(f.z);
        __nv_bfloat16 hw = __float2bfloat16_rn(f.w);
        __nv_bfloat16 lx = __float2bfloat16_rn(f.x - __bfloat162float(hx));
        __nv_bfloat16 ly = __float2bfloat16_rn(f.y - __bfloat162float(hy));
        __nv_bfloat16 lz = __float2bfloat16_rn(f.z - __bfloat162float(hz));
        __nv_bfloat16 lw = __float2bfloat16_rn(f.w - __bfloat162float(hw));

        unsigned* base = (unsigned*)(g_Axl + m * 8192 + j * 32 + 2 * q);
        base[0]  = pack_bf2(hx, hy);   // sp0 hi
        base[4]  = pack_bf2(lx, ly);   // sp0 lo
        base[8]  = pack_bf2(hz, hw);   // sp1 hi
        base[12] = pack_bf2(lz, lw);   // sp1 lo
    }
}

// ---------------------------------------------------------------------------
// Kernel 2: split-K GEMM.  CTA: 4 warps, warp = M64 x N32.  grid (86, 8).
// A: cp.async double-buffer (v3 pipeline).  B: global -> regs, rolling 2-slot.
// Epilogue: atomicAdd(scale*acc) into bias-initialized out.
// ---------------------------------------------------------------------------
#define MMA16816(d, a0, a1, a2, a3, b)                                          \
    asm volatile(                                                               \
        "mma.sync.aligned.m16n8k16.row.col.f32.bf16.bf16.f32 "                  \
        "{%0,%1,%2,%3}, {%4,%5,%6,%7}, {%8,%9}, {%0,%1,%2,%3};\n"               \
        : "+f"(d[0]), "+f"(d[1]), "+f"(d[2]), "+f"(d[3])                        \
        : "r"(a0), "r"(a1), "r"(a2), "r"(a3), "r"(b), "r"(b))

// A stage copy: 64 rows x 128 keff bf16 (256B/row) = 1024 x 16B; 128 thr x 8.
__device__ __forceinline__ void issue_a(uint32_t adst0, const __nv_bfloat16* agsrc,
                                        int kt, int buf) {
    #pragma unroll
    for (int j = 0; j < 8; ++j) {
        uint32_t d = adst0 + buf * (M_DIM * SA * 2) + j * (8 * SA * 2);
        const void* s = agsrc + kt * BKE + (size_t)j * 8 * 8192;
        asm volatile("cp.async.ca.shared.global [%0], [%1], 16;\n"
                     :: "r"(d), "l"(s));
    }
}

__global__ __launch_bounds__(THREADS, 3)
void qgemm_kernel(const int* __restrict__ wq,
                  const float* __restrict__ wscale,
                  float* __restrict__ out) {
    __shared__ __align__(16) __nv_bfloat16 As[2][M_DIM * SA];

    const int tid  = threadIdx.x;
    const int lane = tid & 31;
    const int wid  = tid >> 5;      // 0..3 = n-tile
    const int qp   = lane & 3;
    const int g    = lane >> 2;
    const int bn0   = blockIdx.x * BN;
    const int split = blockIdx.y;

    uint32_t sb;
    { void* p = (void*)As;
      asm("{.reg .u64 t; cvta.to.shared.u64 t, %1; cvt.u32.u64 %0, t;}"
          : "=r"(sb) : "l"(p)); }

    // ---- A cp.async mapping: thread copies 8 x 16B per stage
    const int acol = tid & 15;            // 16B chunk within keff-128 row
    const int arow = tid >> 4;            // base row (8 rows), +8 per j
    const __nv_bfloat16* agsrc = g_Axl + (size_t)arow * 8192 + split * (KSR * 2) + acol * 8;
    const uint32_t adst0 = sb + (uint32_t)((arow * SA + acol * 8) * 2);

    // ---- B base: row for frag fn = bn0 + wid*32 + fn*8 + g
    const int* wgb = wq + (size_t)(bn0 + wid * 32 + g) * K_DIM + split * KSR + 4 * qp;

    // rolling 2-slot B buffer: slot = j & 1
    int4 Bn[4][2];

    // ---- prologue: A stage 0; B j0 -> slot0, j1 -> slot1
    issue_a(adst0, agsrc, 0, 0);
    asm volatile("cp.async.commit_group;\n");
    #pragma unroll
    for (int fn = 0; fn < 4; ++fn) {
        const int* r = wgb + (size_t)fn * 8 * K_DIM;
        Bn[fn][0] = *(const int4*)(r);
        Bn[fn][1] = *(const int4*)(r + 16);
    }

    float acc[4][4][4];
    #pragma unroll
    for (int a = 0; a < 4; ++a)
        #pragma unroll
        for (int b = 0; b < 4; ++b)
            #pragma unroll
            for (int c = 0; c < 4; ++c) acc[a][b][c] = 0.0f;

    const uint32_t aptr = sb + (uint32_t)(((lane & 15) * SA + (lane >> 4) * 8) * 2);

    for (int kt = 0; kt < NST; ++kt) {
        if (kt + 1 < NST) issue_a(adst0, agsrc, kt + 1, (kt + 1) & 1);
        asm volatile("cp.async.commit_group;\n");
        if (kt + 1 < NST) asm volatile("cp.async.wait_group 1;\n");
        else              asm volatile("cp.async.wait_group 0;\n");
        __syncthreads();

        const uint32_t abuf = aptr + (kt & 1) * (M_DIM * SA * 2);
        const bool pf = (kt + 1 < NST);
        const int kcur = kt * BKR, knext = (kt + 1) * BKR;

        #pragma unroll
        for (int s = 0; s < 8; ++s) {
            const int j = s >> 1;
            const int slot = j & 1;
            unsigned bb[4];
            #pragma unroll
            for (int fn = 0; fn < 4; ++fn) {
                int vx, vy;
                if ((s & 1) == 0) { vx = Bn[fn][slot].x; vy = Bn[fn][slot].y; }
                else              { vx = Bn[fn][slot].z; vy = Bn[fn][slot].w; }
                float f0 = (float)vx, f1 = (float)vy;
                asm("cvt.rn.bf16x2.f32 %0, %1, %2;" : "=r"(bb[fn]) : "f"(f1), "f"(f0));
            }
            // rolling refills after each slot's last use (odd s):
            // s=1: slot0 <- j2 (this stage); s=3: slot1 <- j3 (this stage);
            // s=5: slot0 <- next j0;         s=7: slot1 <- next j1.
            if (s == 1) {
                #pragma unroll
                for (int fn = 0; fn < 4; ++fn)
                    Bn[fn][0] = *(const int4*)(wgb + (size_t)fn * 8 * K_DIM + kcur + 32);
            } else if (s == 3) {
                #pragma unroll
                for (int fn = 0; fn < 4; ++fn)
                    Bn[fn][1] = *(const int4*)(wgb + (size_t)fn * 8 * K_DIM + kcur + 48);
            } else if (s == 5 && pf) {
                #pragma unroll
                for (int fn = 0; fn < 4; ++fn)
                    Bn[fn][0] = *(const int4*)(wgb + (size_t)fn * 8 * K_DIM + knext);
            } else if (s == 7 && pf) {
                #pragma unroll
                for (int fn = 0; fn < 4; ++fn)
                    Bn[fn][1] = *(const int4*)(wgb + (size_t)fn * 8 * K_DIM + knext + 16);
            }

            #pragma unroll
            for (int fm = 0; fm < 4; ++fm) {
                unsigned a0, a1, a2, a3;
                asm volatile(
                    "ldmatrix.sync.aligned.m8n8.x4.shared.b16 {%0,%1,%2,%3}, [%4];\n"
                    : "=r"(a0), "=r"(a1), "=r"(a2), "=r"(a3)
                    : "r"(abuf + fm * (16 * SA * 2) + s * 32));
                MMA16816(acc[fm][0], a0, a1, a2, a3, bb[0]);
                MMA16816(acc[fm][1], a0, a1, a2, a3, bb[1]);
                MMA16816(acc[fm][2], a0, a1, a2, a3, bb[2]);
                MMA16816(acc[fm][3], a0, a1, a2, a3, bb[3]);
            }
        }
        __syncthreads();
    }

    // ---- epilogue: atomicAdd scale*acc into bias-initialized out
    const float sc = wscale[0];
    #pragma unroll
    for (int fm = 0; fm < 4; ++fm) {
        const int m0 = fm * 16 + g;
        #pragma unroll
        for (int fn = 0; fn < 4; ++fn) {
            const int n = bn0 + wid * 32 + fn * 8 + 2 * qp;
            atomicAdd(out + (size_t)m0 * N_DIM + n,           sc * acc[fm][fn][0]);
            atomicAdd(out + (size_t)m0 * N_DIM + n + 1,       sc * acc[fm][fn][1]);
            atomicAdd(out + (size_t)(m0 + 8) * N_DIM + n,     sc * acc[fm][fn][2]);
            atomicAdd(out + (size_t)(m0 + 8) * N_DIM + n + 1, sc * acc[fm][fn][3]);
        }
    }
}

extern "C" void kernel_launch(void* const* d_in, const int* in_sizes, int n_in,
                              void* d_out, int out_size) {
    const float* x      = (const float*)d_in[0];
    const int*   wq     = (const int*)  d_in[1];
    const float* wscale = (const float*)d_in[2];
    const float* bias   = (const float*)d_in[3];
    float*       out    = (float*)d_out;

    prep_kernel<<<688, 256>>>(x, bias, out);
    qgemm_kernel<<<dim3(N_DIM / BN, SPLITS), THREADS>>>(wq, wscale, out);
}